// round 11
// baseline (speedup 1.0000x reference)
#include <cuda_runtime.h>

#define B 64
#define CIN 512
#define HIDE 128
#define OP 512
#define HW 4096   // 64*64
#define SENT 0x7FC00123u   // quiet-NaN payload; finite pooled means never equal it

__device__ float g_y[B * CIN];

__device__ __forceinline__ float ld_cg(const float* p) {
    float v;
    asm volatile("ld.global.cg.f32 %0, [%1];" : "=f"(v) : "l"(p));
    return v;
}
__device__ __forceinline__ void prefetch_l2(const void* p) {
    asm volatile("prefetch.global.L2 [%0];" :: "l"(p));
}

// sentinel fill (8192 float4 = 128KB)
__global__ __launch_bounds__(256) void init_kernel() {
    cudaTriggerProgrammaticLaunchCompletion();
    const int i = blockIdx.x * 256 + threadIdx.x;
    const float s = __uint_as_float(SENT);
    reinterpret_cast<float4*>(g_y)[i] = make_float4(s, s, s, s);
}

// ---------------------------------------------------------------------------
// Kernel 1: global average pool — EXACT proven body (87.6% DRAM), PDL trigger.
// ---------------------------------------------------------------------------
__global__ __launch_bounds__(256) void pool_kernel(const float* __restrict__ x,
                                                   float* __restrict__ y) {
    cudaTriggerProgrammaticLaunchCompletion();

    const int row = blockIdx.x;
    const float4* p = reinterpret_cast<const float4*>(x + (size_t)row * HW);
    const int t = threadIdx.x;

    float s = 0.0f;
#pragma unroll
    for (int i = 0; i < 4; i++) {
        float4 v = __ldcs(&p[t + i * 256]);
        s += (v.x + v.y) + (v.z + v.w);
    }
#pragma unroll
    for (int o = 16; o > 0; o >>= 1) s += __shfl_xor_sync(0xFFFFFFFFu, s, o);

    __shared__ float sm[8];
    if ((t & 31) == 0) sm[t >> 5] = s;
    __syncthreads();
    if (t < 8) {
        float v = sm[t];
#pragma unroll
        for (int o = 4; o > 0; o >>= 1) v += __shfl_xor_sync(0x000000FFu, v, o);
        if (t == 0) y[row] = v * (1.0f / (float)HW);
    }
}

// ---------------------------------------------------------------------------
// Kernel 2: AGCA head. PDL-launched, NO grid sync — each block gates on its
// own batch's pooled values via sentinel polling (fence-free: the datum is
// the signal). Prefetches weights into L2 before/while waiting.
// One block per batch, 256 threads.
// ---------------------------------------------------------------------------
__global__ __launch_bounds__(256) void head_kernel(const float* __restrict__ W1,
                                                   const float* __restrict__ A2,
                                                   const float* __restrict__ w2p,
                                                   const float* __restrict__ w3p,
                                                   const float* __restrict__ W4,
                                                   float* __restrict__ out) {
    const int b    = blockIdx.x;
    const int tid  = threadIdx.x;
    const int wid  = tid >> 5;
    const int lane = tid & 31;

    __shared__ float ys[CIN];
    __shared__ float y1s[HIDE];
    __shared__ float a1s[HIDE];
    __shared__ float y3s[HIDE];
    __shared__ float red[8];

    // prefetch this block's 1/64 slice of the weights while data is pending
    {
        const char* w1c = (const char*)W1;
        const char* w4c = (const char*)W4;
        const char* a2c = (const char*)A2;
        if (tid < 32) {
            prefetch_l2(w1c + ((size_t)b * 32 + tid) * 128);
        } else if (tid < 64) {
            prefetch_l2(w4c + ((size_t)b * 32 + (tid - 32)) * 128);
        } else if (tid < 72) {
            prefetch_l2(a2c + ((size_t)b * 8 + (tid - 64)) * 128);
        }
    }

    // fence-free wait: poll own elements until non-sentinel
    float* gyb = g_y + b * CIN;
    {
        float a0 = ld_cg(gyb + tid);
        while (__float_as_uint(a0) == SENT) { __nanosleep(256); a0 = ld_cg(gyb + tid); }
        float a1 = ld_cg(gyb + tid + 256);
        while (__float_as_uint(a1) == SENT) { __nanosleep(256); a1 = ld_cg(gyb + tid + 256); }
        ys[tid]       = a0;
        ys[tid + 256] = a1;
    }
    __syncthreads();

    // re-arm sentinels for the next replay (pool of next call is stream-ordered
    // after this kernel, so no race)
    gyb[tid]       = __uint_as_float(SENT);
    gyb[tid + 256] = __uint_as_float(SENT);

    // ---- GEMV1: warp wid owns h in [wid*16, wid*16+16): 2 passes of 8 ----
#pragma unroll
    for (int pass = 0; pass < 2; pass++) {
        const int h0 = (wid << 4) + (pass << 3);
        float acc[8];
#pragma unroll
        for (int i = 0; i < 8; i++) acc[i] = 0.0f;
#pragma unroll
        for (int k = 0; k < CIN / 32; k++) {
            const int c = lane + (k << 5);
            const float yv = ys[c];
#pragma unroll
            for (int i = 0; i < 8; i++)
                acc[i] += yv * __ldg(&W1[(size_t)(h0 + i) * CIN + c]);
        }
#pragma unroll
        for (int o = 16; o > 0; o >>= 1)
#pragma unroll
            for (int i = 0; i < 8; i++)
                acc[i] += __shfl_xor_sync(0xFFFFFFFFu, acc[i], o);
        if (lane == 0)
#pragma unroll
            for (int i = 0; i < 8; i++) y1s[h0 + i] = acc[i];
    }
    __syncthreads();

    // ---- softmax(w2 * y1) over 128 channels (warps 0..3) ----
    const float w2 = __ldg(w2p);
    if (tid < HIDE) {
        const float z = w2 * y1s[tid];
        float m = z;
#pragma unroll
        for (int o = 16; o > 0; o >>= 1) m = fmaxf(m, __shfl_xor_sync(0xFFFFFFFFu, m, o));
        if (lane == 0) red[wid] = m;
    }
    __syncthreads();
    if (tid < HIDE) {
        const float m = fmaxf(fmaxf(red[0], red[1]), fmaxf(red[2], red[3]));
        const float e = expf(w2 * y1s[tid] - m);
        a1s[tid] = e;
        float ssum = e;
#pragma unroll
        for (int o = 16; o > 0; o >>= 1) ssum += __shfl_xor_sync(0xFFFFFFFFu, ssum, o);
        if (lane == 0) red[4 + wid] = ssum;
    }
    __syncthreads();

    // ---- y2/y3: h = tid (<128); A2 coalesced over h ----
    if (tid < HIDE) {
        const float ssum = (red[4] + red[5]) + (red[6] + red[7]);
        const float a1n = a1s[tid] / ssum;
        float t = y1s[tid] * a1n;
#pragma unroll 16
        for (int j = 0; j < HIDE; j++) t += y1s[j] * __ldg(&A2[j * HIDE + tid]);
        const float w3 = __ldg(w3p);
        y3s[tid] = fmaxf(w3 * t, 0.0f);
    }
    __syncthreads();

    // ---- GEMV4: warp wid owns o in [wid*64, wid*64+64): 8 passes of 8 ----
#pragma unroll
    for (int pass = 0; pass < 8; pass++) {
        const int o0 = (wid << 6) + (pass << 3);
        float acc[8];
#pragma unroll
        for (int i = 0; i < 8; i++) acc[i] = 0.0f;
#pragma unroll
        for (int k = 0; k < HIDE / 32; k++) {
            const int j = lane + (k << 5);
            const float yv = y3s[j];
#pragma unroll
            for (int i = 0; i < 8; i++)
                acc[i] += yv * __ldg(&W4[(size_t)(o0 + i) * HIDE + j]);
        }
#pragma unroll
        for (int off = 16; off > 0; off >>= 1)
#pragma unroll
            for (int i = 0; i < 8; i++)
                acc[i] += __shfl_xor_sync(0xFFFFFFFFu, acc[i], off);
        if (lane == 0) {
#pragma unroll
            for (int i = 0; i < 8; i++)
                out[b * OP + o0 + i] = 1.0f / (1.0f + expf(-acc[i]));
        }
    }
}

extern "C" void kernel_launch(void* const* d_in, const int* in_sizes, int n_in,
                              void* d_out, int out_size) {
    const float* x  = (const float*)d_in[0];
    const float* W1 = (const float*)d_in[1];
    const float* A2 = (const float*)d_in[2];
    const float* w2 = (const float*)d_in[3];
    const float* w3 = (const float*)d_in[4];
    const float* W4 = (const float*)d_in[5];
    float* out = (float*)d_out;

    float* yscratch;
    cudaGetSymbolAddress((void**)&yscratch, g_y);

    // 0) sentinel fill (tiny; PDL trigger lets pool start immediately after
    //    its writes are issued). NOTE: pool only OVERWRITES g_y, and head
    //    gates on non-sentinel, so init must fully precede pool — enforced
    //    by stream order (init has no PDL-dependent successor semantics
    //    issue: pool is PDL-launched under init, but init's 128KB write
    //    finishes in <1us while pool's first useful write is >1us away).
    init_kernel<<<32, 256>>>();

    // 1) pool, PDL-launched (starts as init drains)
    {
        cudaLaunchConfig_t cfg = {};
        cfg.gridDim = dim3(B * CIN);
        cfg.blockDim = dim3(256);
        cfg.stream = 0;
        cudaLaunchAttribute attr[1];
        attr[0].id = cudaLaunchAttributeProgrammaticStreamSerialization;
        attr[0].val.programmaticStreamSerializationAllowed = 1;
        cfg.attrs = attr;
        cfg.numAttrs = 1;
        cudaLaunchKernelEx(&cfg, pool_kernel, x, yscratch);
    }

    // 2) head, PDL-launched; blocks self-gate on their batch's data
    {
        cudaLaunchConfig_t cfg = {};
        cfg.gridDim = dim3(B);
        cfg.blockDim = dim3(256);
        cfg.stream = 0;
        cudaLaunchAttribute attr[1];
        attr[0].id = cudaLaunchAttributeProgrammaticStreamSerialization;
        attr[0].val.programmaticStreamSerializationAllowed = 1;
        cfg.attrs = attr;
        cfg.numAttrs = 1;
        cudaLaunchKernelEx(&cfg, head_kernel, W1, A2, w2, w3, W4, out);
    }
}

// round 12
// speedup vs baseline: 1.5034x; 1.5034x over previous
#include <cuda_runtime.h>

#define B 64
#define CIN 512
#define HIDE 128
#define OP 512
#define HW 4096   // 64*64

// scratch for pooled y [B, CIN]
__device__ float g_y[B * CIN];

__device__ __forceinline__ void prefetch_l2(const void* p) {
    asm volatile("prefetch.global.L2 [%0];" :: "l"(p));
}

// ---------------------------------------------------------------------------
// Kernel 1: global average pool — EXACT proven body (87.6% DRAM).
// ---------------------------------------------------------------------------
__global__ __launch_bounds__(256) void pool_kernel(const float* __restrict__ x,
                                                   float* __restrict__ y) {
    cudaTriggerProgrammaticLaunchCompletion();

    const int row = blockIdx.x;
    const float4* p = reinterpret_cast<const float4*>(x + (size_t)row * HW);
    const int t = threadIdx.x;

    float s = 0.0f;
#pragma unroll
    for (int i = 0; i < 4; i++) {
        float4 v = __ldcs(&p[t + i * 256]);
        s += (v.x + v.y) + (v.z + v.w);
    }
#pragma unroll
    for (int o = 16; o > 0; o >>= 1) s += __shfl_xor_sync(0xFFFFFFFFu, s, o);

    __shared__ float sm[8];
    if ((t & 31) == 0) sm[t >> 5] = s;
    __syncthreads();
    if (t < 8) {
        float v = sm[t];
#pragma unroll
        for (int o = 4; o > 0; o >>= 1) v += __shfl_xor_sync(0x000000FFu, v, o);
        if (t == 0) y[row] = v * (1.0f / (float)HW);
    }
}

// ---------------------------------------------------------------------------
// Kernel 2: fused AGCA head, minimal serial-DRAM-round critical path.
// One block per batch, 1024 threads, PDL + weight prefetch before grid sync.
// ---------------------------------------------------------------------------
__global__ __launch_bounds__(1024) void head_kernel(const float* __restrict__ y,
                                                    const float* __restrict__ W1,
                                                    const float* __restrict__ A2,
                                                    const float* __restrict__ w2p,
                                                    const float* __restrict__ w3p,
                                                    const float* __restrict__ W4,
                                                    float* __restrict__ out) {
    const int b    = blockIdx.x;
    const int tid  = threadIdx.x;
    const int wid  = tid >> 5;
    const int lane = tid & 31;

    // ---- L2 prefetch of this block's 1/64 slice of the weights ----
    {
        const char* w1c = (const char*)W1;
        const char* w4c = (const char*)W4;
        const char* a2c = (const char*)A2;
        if (tid < 32) {
            prefetch_l2(w1c + ((size_t)b * 32 + tid) * 128);
        } else if (tid < 64) {
            prefetch_l2(w4c + ((size_t)b * 32 + (tid - 32)) * 128);
        } else if (tid < 72) {
            prefetch_l2(a2c + ((size_t)b * 8 + (tid - 64)) * 128);
        }
    }

    cudaGridDependencySynchronize();

    __shared__ float ys[CIN];
    __shared__ float y1s[HIDE];
    __shared__ float a1s[HIDE];
    __shared__ float y3s[HIDE];
    __shared__ float part[8][HIDE];   // A2 partial sums
    __shared__ float red[8];

    if (tid < CIN) ys[tid] = y[b * CIN + tid];
    __syncthreads();

    // ---- GEMV1: warp wid -> h = wid*4 + {0..3}; 64 batched loads, 1 round ----
    {
        const int h0 = wid << 2;
        const float* r0 = W1 + (size_t)(h0 + 0) * CIN;
        const float* r1 = W1 + (size_t)(h0 + 1) * CIN;
        const float* r2 = W1 + (size_t)(h0 + 2) * CIN;
        const float* r3 = W1 + (size_t)(h0 + 3) * CIN;
        float a0 = 0.f, a1 = 0.f, a2 = 0.f, a3 = 0.f;
#pragma unroll
        for (int k = 0; k < CIN / 32; k++) {
            const int c = lane + (k << 5);
            const float yv = ys[c];
            a0 += yv * __ldg(r0 + c);
            a1 += yv * __ldg(r1 + c);
            a2 += yv * __ldg(r2 + c);
            a3 += yv * __ldg(r3 + c);
        }
#pragma unroll
        for (int o = 16; o > 0; o >>= 1) {
            a0 += __shfl_xor_sync(0xFFFFFFFFu, a0, o);
            a1 += __shfl_xor_sync(0xFFFFFFFFu, a1, o);
            a2 += __shfl_xor_sync(0xFFFFFFFFu, a2, o);
            a3 += __shfl_xor_sync(0xFFFFFFFFu, a3, o);
        }
        if (lane == 0) {
            y1s[h0 + 0] = a0; y1s[h0 + 1] = a1;
            y1s[h0 + 2] = a2; y1s[h0 + 3] = a3;
        }
    }
    __syncthreads();

    // ---- A2 partials IN PARALLEL with softmax start:
    //      thread (h = tid&127, slice s = tid>>7) sums j in [16s, 16s+16) ----
    {
        const int h = tid & (HIDE - 1);
        const int s = tid >> 7;
        const int j0 = s << 4;
        float t = 0.0f;
#pragma unroll
        for (int j = 0; j < 16; j++)
            t += y1s[j0 + j] * __ldg(&A2[(j0 + j) * HIDE + h]);
        part[s][h] = t;
    }

    // ---- softmax(w2 * y1) over 128 channels (warps 0..3) ----
    const float w2 = __ldg(w2p);
    if (tid < HIDE) {
        const float z = w2 * y1s[tid];
        float m = z;
#pragma unroll
        for (int o = 16; o > 0; o >>= 1) m = fmaxf(m, __shfl_xor_sync(0xFFFFFFFFu, m, o));
        if (lane == 0) red[wid] = m;
    }
    __syncthreads();
    if (tid < HIDE) {
        const float m = fmaxf(fmaxf(red[0], red[1]), fmaxf(red[2], red[3]));
        const float e = expf(w2 * y1s[tid] - m);
        a1s[tid] = e;
        float ssum = e;
#pragma unroll
        for (int o = 16; o > 0; o >>= 1) ssum += __shfl_xor_sync(0xFFFFFFFFu, ssum, o);
        if (lane == 0) red[4 + wid] = ssum;
    }
    __syncthreads();

    // ---- combine: y3[h] = relu(w3 * (y1*a1 + sum_s part[s][h])) ----
    if (tid < HIDE) {
        const float ssum = (red[4] + red[5]) + (red[6] + red[7]);
        const float a1n = a1s[tid] / ssum;
        float t = y1s[tid] * a1n;
        // fixed-order tree over 8 slices (deterministic)
        float p0 = part[0][tid] + part[1][tid];
        float p1 = part[2][tid] + part[3][tid];
        float p2 = part[4][tid] + part[5][tid];
        float p3 = part[6][tid] + part[7][tid];
        t += (p0 + p1) + (p2 + p3);
        const float w3 = __ldg(w3p);
        y3s[tid] = fmaxf(w3 * t, 0.0f);
    }
    __syncthreads();

    // ---- GEMV4: warp wid owns 16 outputs, single pass (64 batched loads) ----
    {
        const int o_base = wid << 4;
        float acc[16];
#pragma unroll
        for (int i = 0; i < 16; i++) acc[i] = 0.0f;
#pragma unroll
        for (int k = 0; k < HIDE / 32; k++) {
            const int j = lane + (k << 5);
            const float yv = y3s[j];
#pragma unroll
            for (int i = 0; i < 16; i++)
                acc[i] += yv * __ldg(&W4[(size_t)(o_base + i) * HIDE + j]);
        }
#pragma unroll
        for (int off = 16; off > 0; off >>= 1) {
#pragma unroll
            for (int i = 0; i < 16; i++)
                acc[i] += __shfl_xor_sync(0xFFFFFFFFu, acc[i], off);
        }
        if (lane == 0) {
#pragma unroll
            for (int i = 0; i < 16; i++)
                out[b * OP + o_base + i] = 1.0f / (1.0f + expf(-acc[i]));
        }
    }
}

extern "C" void kernel_launch(void* const* d_in, const int* in_sizes, int n_in,
                              void* d_out, int out_size) {
    const float* x  = (const float*)d_in[0];
    const float* W1 = (const float*)d_in[1];
    const float* A2 = (const float*)d_in[2];
    const float* w2 = (const float*)d_in[3];
    const float* w3 = (const float*)d_in[4];
    const float* W4 = (const float*)d_in[5];
    float* out = (float*)d_out;

    float* yscratch;
    cudaGetSymbolAddress((void**)&yscratch, g_y);

    pool_kernel<<<B * CIN, 256>>>(x, yscratch);

    cudaLaunchConfig_t cfg = {};
    cfg.gridDim = dim3(B);
    cfg.blockDim = dim3(1024);
    cfg.dynamicSmemBytes = 0;
    cfg.stream = 0;
    cudaLaunchAttribute attr[1];
    attr[0].id = cudaLaunchAttributeProgrammaticStreamSerialization;
    attr[0].val.programmaticStreamSerializationAllowed = 1;
    cfg.attrs = attr;
    cfg.numAttrs = 1;
    cudaLaunchKernelEx(&cfg, head_kernel, (const float*)yscratch, W1, A2, w2, w3, W4, out);
}